// round 4
// baseline (speedup 1.0000x reference)
#include <cuda_runtime.h>
#include <cuda_bf16.h>

#define NN 320
#define DD 256

// Scratch (allocation-free device globals)
__device__ float  g_L[NN * NN];       // logits (bit-exact symmetric)
__device__ float  g_E[NN * NN];       // exp(logits)
__device__ float  g_ys[NN];           // sorted y_times
__device__ int    g_perm[NN];         // sorted pos -> original index
__device__ int    g_se[NN];           // event class in sorted order
__device__ int    g_gt[NN];           // per k: first sorted m with ys[m]-yk > 0
__device__ int    g_geq[NN];          // per k: first sorted m with !(ys[m]-yk < 0)
__device__ float2 g_P[NN * (NN + 1)]; // per-row class-split E prefix sums
__device__ int    g_cnt[NN + 1];      // class-count prefix, packed c1<<10 | c0
__device__ float  g_loss[NN];
__device__ float  g_pos[NN];
__device__ int    g_ctr;

// TABLE rows packed: weight code c in {0,1,2} (weight = c*0.5) at bits [2v+1:2v],
// v = td + 3*e, td in {1(lower),2(middle),3(upper)}.
__constant__ int c_rb[7] = {8852, 5460, 4692, 5460, 5716, 4436, 8852};

// Packed fp32x2 helpers (sm_103a FFMA2 path — only reachable via PTX)
__device__ __forceinline__ void dsq_acc(unsigned long long& acc,
                                        unsigned long long x,
                                        unsigned long long ny) {
    unsigned long long d;
    asm("add.rn.f32x2 %0, %1, %2;" : "=l"(d) : "l"(x), "l"(ny));
    asm("fma.rn.f32x2 %0, %1, %1, %0;" : "+l"(acc) : "l"(d));
}
__device__ __forceinline__ float dsum(unsigned long long acc) {
    unsigned lo, hi;
    asm("mov.b64 {%0, %1}, %2;" : "=r"(lo), "=r"(hi) : "l"(acc));
    return __uint_as_float(lo) + __uint_as_float(hi);
}

// ---------------------------------------------------------------------------
// Kernel 1: distances (blocks 0..99, f32x2-packed 2x2 micro-tiles over 32x32
// output tiles, K staged in 2 chunks) + exact rank sort / bounds (blocks
// 100,101). Row-max subtraction in the reference is a no-op (diag logit == 0
// == row max); d = x + (-y) is IEEE-identical to x - y, and (i,j)/(j,i)
// square the negated diff -> bit-exact symmetric L.
// ---------------------------------------------------------------------------
__global__ void dist_kernel(const float* __restrict__ F,
                            const float* __restrict__ yt,
                            const int* __restrict__ ye) {
    __shared__ float2 sA[64][33];   // [dpair][i], pad 33 kills STS conflicts
    __shared__ float2 sB[64][33];   // negated B tile
    __shared__ float  s_y[NN];
    int tx = threadIdx.x, ty = threadIdx.y;       // 16 x 16
    int tid = ty * 16 + tx;
    int b = blockIdx.x;

    if (b >= 100) {
        // --- sort / bounds block: 160 anchors each, O(N) exact counts ---
        for (int e = tid; e < NN; e += 256) s_y[e] = yt[e];
        __syncthreads();
        if (tid < 160) {
            int e = (b - 100) * 160 + tid;
            float v = s_y[e];
            int rank = 0, gt = 0, geq = 0;
#pragma unroll 8
            for (int j = 0; j < NN; j++) {
                float w = s_y[j];
                float d = w - v;                       // same float expr as reference pld
                rank += (w < v) || (w == v && j < e);  // unique tie-broken rank
                gt  += !(d > 0.0f);
                geq += (d < 0.0f);
            }
            g_ys[rank] = v; g_perm[rank] = e; g_se[rank] = __ldg(&ye[e]);
            g_gt[e] = gt; g_geq[e] = geq;
        }
        return;
    }

    int bi = (b / 10) * 32, bj = (b % 10) * 32;
    int row = tid >> 3;            // 0..31
    int col0 = (tid & 7) << 4;     // 0,16,...,112 (floats within 128-chunk)

    unsigned long long a00 = 0ull, a01 = 0ull, a10 = 0ull, a11 = 0ull;

    for (int s = 0; s < 2; s++) {
        const float* pA = F + (bi + row) * DD + s * 128 + col0;
        const float* pB = F + (bj + row) * DD + s * 128 + col0;
#pragma unroll
        for (int q = 0; q < 4; q++) {
            float4 av = *(const float4*)(pA + 4 * q);
            float4 bv = *(const float4*)(pB + 4 * q);
            int dp = (col0 + 4 * q) >> 1;
            sA[dp][row]     = make_float2(av.x, av.y);
            sA[dp + 1][row] = make_float2(av.z, av.w);
            sB[dp][row]     = make_float2(-bv.x, -bv.y);
            sB[dp + 1][row] = make_float2(-bv.z, -bv.w);
        }
        __syncthreads();
#pragma unroll 16
        for (int dd = 0; dd < 64; dd++) {
            unsigned long long x0 = *(const unsigned long long*)&sA[dd][2 * ty];
            unsigned long long x1 = *(const unsigned long long*)&sA[dd][2 * ty + 1];
            unsigned long long y0 = *(const unsigned long long*)&sB[dd][2 * tx];
            unsigned long long y1 = *(const unsigned long long*)&sB[dd][2 * tx + 1];
            dsq_acc(a00, x0, y0);
            dsq_acc(a01, x0, y1);
            dsq_acc(a10, x1, y0);
            dsq_acc(a11, x1, y1);
        }
        __syncthreads();
    }

    int i0 = bi + 2 * ty, j0 = bj + 2 * tx;
    float L;
    L = -0.5f * sqrtf(dsum(a00)); g_L[i0 * NN + j0]           = L; g_E[i0 * NN + j0]           = __expf(L);
    L = -0.5f * sqrtf(dsum(a01)); g_L[i0 * NN + j0 + 1]       = L; g_E[i0 * NN + j0 + 1]       = __expf(L);
    L = -0.5f * sqrtf(dsum(a10)); g_L[(i0 + 1) * NN + j0]     = L; g_E[(i0 + 1) * NN + j0]     = __expf(L);
    L = -0.5f * sqrtf(dsum(a11)); g_L[(i0 + 1) * NN + j0 + 1] = L; g_E[(i0 + 1) * NN + j0 + 1] = __expf(L);
}

// ---------------------------------------------------------------------------
// Kernel 2: per-row class-split prefix sums (warp-shuffle scan). Block 0 also
// builds the global class-count prefix and resets the completion counter.
// ---------------------------------------------------------------------------
__global__ void scan_kernel() {
    __shared__ float ws0[10], ws1[10], wo0[10], wo1[10];
    __shared__ int   wsi[10], woi[10];
    int i = blockIdx.x, t = threadIdx.x;
    int lane = t & 31, w = t >> 5;
    if (i == 0 && t == 0) g_ctr = 0;

    int pj = g_perm[t];
    int cls = g_se[t];
    float Ev = (pj == i) ? 0.f : __ldg(&g_E[i * NN + pj]);   // eye mask folded
    float x0 = cls ? 0.f : Ev;
    float x1 = cls ? Ev : 0.f;
    int   xc = cls ? (1 << 10) : 1;

#pragma unroll
    for (int off = 1; off < 32; off <<= 1) {
        float a0 = __shfl_up_sync(0xffffffffu, x0, off);
        float a1 = __shfl_up_sync(0xffffffffu, x1, off);
        int   ac = __shfl_up_sync(0xffffffffu, xc, off);
        if (lane >= off) { x0 += a0; x1 += a1; xc += ac; }
    }
    if (lane == 31) { ws0[w] = x0; ws1[w] = x1; wsi[w] = xc; }
    __syncthreads();
    if (t == 0) {
        float r0 = 0.f, r1 = 0.f; int ri = 0;
#pragma unroll
        for (int q = 0; q < 10; q++) {
            wo0[q] = r0; wo1[q] = r1; woi[q] = ri;
            r0 += ws0[q]; r1 += ws1[q]; ri += wsi[q];
        }
    }
    __syncthreads();
    x0 += wo0[w]; x1 += wo1[w];
    float2* Prow = g_P + i * (NN + 1);
    Prow[t + 1] = make_float2(x0, x1);
    if (t == 0) Prow[0] = make_float2(0.f, 0.f);
    if (i == 0) {
        g_cnt[t + 1] = xc + woi[w];
        if (t == 0) g_cnt[0] = 0;
    }
}

// ---------------------------------------------------------------------------
// Kernel 3: block per anchor k, thread per row i. 2 binary searches + prefix
// assembly; exact integer-count validity; block reduce -> loss_k; last block
// done produces the final scalar (deterministic fixed-order reduction).
// ---------------------------------------------------------------------------
__global__ void lossk_kernel(const float* __restrict__ yt,
                             const int* __restrict__ ye,
                             float* __restrict__ out) {
    __shared__ float s_ys[NN];
    __shared__ int   s_cnt[NN + 1];
    __shared__ int   s_rb[7];
    __shared__ float rS[10], rC[10];
    __shared__ int   s_last;

    int k = blockIdx.x, t = threadIdx.x;
    int lane = t & 31, w = t >> 5;
    s_ys[t] = g_ys[t];
    s_cnt[t] = g_cnt[t];
    if (t == 0) s_cnt[NN] = g_cnt[NN];
    if (t < 7) s_rb[t] = c_rb[t];
    __syncthreads();

    float yk = __ldg(&yt[k]);
    int   ek = __ldg(&ye[k]);
    int   gt = g_gt[k], geq = g_geq[k];

    int i = t;
    float yi = yt[i];
    int   ei = ye[i];
    float pi = yi - yk;
    float a = fabsf(pi), na = -a;

    int base = ei + 10 * ek;
    int cid = (pi > 0.f) ? base : ((pi < 0.f) ? -base : 0);
    int cidx = (cid == -11) ? 0 : (cid == -10) ? 1 : (cid == -1) ? 2 :
               (cid == 0)   ? 3 : (cid == 1)   ? 4 : (cid == 10) ? 5 : 6;
    int rb = s_rb[cidx];

    // hi: first m with ys[m]-yk > a  (identical float expr as reference)
    int first = 0, count = NN;
    while (count > 0) {
        int half = count >> 1, mid = first + half;
        if (!(s_ys[mid] - yk > a)) { first = mid + 1; count -= half + 1; }
        else count = half;
    }
    int hi = first;
    // lo: first m with !(ys[m]-yk < -a)
    first = 0; count = NN;
    while (count > 0) {
        int half = count >> 1, mid = first + half;
        if (s_ys[mid] - yk < na) { first = mid + 1; count -= half + 1; }
        else count = half;
    }
    int lo = first;

    const float2* Prow = g_P + i * (NN + 1);
    float2 Pend = Prow[NN], Phi = Prow[hi], Plo = Prow[lo];
    float2 Pgt = Prow[gt], Pgq = Prow[geq];
    float SU0 = Pend.x - Phi.x, SU1 = Pend.y - Phi.y;
    float SL0 = Plo.x,          SL1 = Plo.y;
    float SM0 = (Phi.x - Plo.x) - (Pgt.x - Pgq.x);
    float SM1 = (Phi.y - Plo.y) - (Pgt.y - Pgq.y);

    float w10 = (float)((rb >> 2)  & 3), w20 = (float)((rb >> 4)  & 3), w30 = (float)((rb >> 6)  & 3);
    float w11 = (float)((rb >> 8)  & 3), w21 = (float)((rb >> 10) & 3), w31 = (float)((rb >> 12) & 3);
    float denom = 0.5f * (w10 * SL0 + w11 * SL1 + w20 * SM0 + w21 * SM1 + w30 * SU0 + w31 * SU1);

    // Exact integer validity: counts of positive-weight elements.
    int cU = s_cnt[NN] - s_cnt[hi];
    int cL = s_cnt[lo];
    int cM = (s_cnt[hi] - s_cnt[lo]) - (s_cnt[gt] - s_cnt[geq]);
    if (pi != 0.f) cM -= (ei ? (1 << 10) : 1);   // i sits in middle, weight 0 (eye)
    int nz = rb | (rb >> 1);
    int vsum = ((nz >> 2) & 1) * (cL & 1023) + ((nz >> 8)  & 1) * (cL >> 10)
             + ((nz >> 4) & 1) * (cM & 1023) + ((nz >> 10) & 1) * (cM >> 10)
             + ((nz >> 6) & 1) * (cU & 1023) + ((nz >> 12) & 1) * (cU >> 10);
    bool valid = (vsum > 0) && (i != k);

    float res = valid ? (__ldg(&g_L[k * NN + i]) - __logf(denom)) : 0.f;  // L symmetric
    float c   = valid ? 1.f : 0.f;

#pragma unroll
    for (int sh = 16; sh > 0; sh >>= 1) {
        res += __shfl_xor_sync(0xffffffffu, res, sh);
        c   += __shfl_xor_sync(0xffffffffu, c,   sh);
    }
    if (lane == 0) { rS[w] = res; rC[w] = c; }
    __syncthreads();
    if (t == 0) {
        float S = 0.f, C = 0.f;
#pragma unroll
        for (int q = 0; q < 10; q++) { S += rS[q]; C += rC[q]; }
        g_loss[k] = (C > 0.f) ? (-S / C) : 0.f;
        g_pos[k]  = (C > 0.f) ? 1.f : 0.f;
        __threadfence();
        int old = atomicAdd(&g_ctr, 1);
        s_last = (old == NN - 1);
    }
    __syncthreads();
    if (s_last) {
        float sa = g_loss[t], sb = g_pos[t];
#pragma unroll
        for (int sh = 16; sh > 0; sh >>= 1) {
            sa += __shfl_xor_sync(0xffffffffu, sa, sh);
            sb += __shfl_xor_sync(0xffffffffu, sb, sh);
        }
        if (lane == 0) { rS[w] = sa; rC[w] = sb; }
        __syncthreads();
        if (t == 0) {
            float S = 0.f, P = 0.f;
#pragma unroll
            for (int q = 0; q < 10; q++) { S += rS[q]; P += rC[q]; }
            out[0] = S / P;
        }
    }
}

extern "C" void kernel_launch(void* const* d_in, const int* in_sizes, int n_in,
                              void* d_out, int out_size) {
    const float* features = (const float*)d_in[0];   // [320, 256] f32
    const float* y_times  = (const float*)d_in[1];   // [320] f32
    const int*   y_events = (const int*)d_in[2];     // [320] i32
    float* out = (float*)d_out;

    dist_kernel<<<102, dim3(16, 16)>>>(features, y_times, y_events);
    scan_kernel<<<NN, NN>>>();
    lossk_kernel<<<NN, NN>>>(y_times, y_events, out);
}